// round 5
// baseline (speedup 1.0000x reference)
#include <cuda_runtime.h>
#include <cuda_bf16.h>
#include <cstdint>

// ---------------------------------------------------------------------------
// LinearAttention via warp-level bf16 HMMA (mma.sync m16n8k16), 3-pass hi/lo
// fp32 emulation, pass-major-outer with single A buffer + pipelined fragments.
//   prep_w : split W_qkv -> bf16 hi/lo
//   ka     : per (b, 64-wide n-tile), 2 CTAs/SM:
//            stage x bf16 hi/lo [c][n]; k-GEMM -> ek(smem); v-GEMM -> v(smem);
//            fused ctx partials; q-GEMM -> softmax p -> g_pt hi/lo
//   kb2    : reduce partials, fold w_out -> M2 bf16 hi/lo
//   kc     : HMMA out-proj (n-tile 64) + bias + GN partials
//   kd     : GroupNorm finalize
// ---------------------------------------------------------------------------

#define Bz     32
#define NN     4096
#define HID    128
#define NHh    4
#define NSPLIT 64
#define SCALE  0.17677669529663687f   // 1/sqrt(32)
#define PADB   136                    // A (and kc-B) bf16 row stride
#define BSTR   72                     // ka B (x) bf16 row stride
#define EKST   70                     // ek/v fp32 row stride

// smem offsets (bytes) -- ka
#define SA     0                      // 35840: A bf16 [128][136] / v fp32 [128][70]
#define SB_H   35840                  // 18432: x hi [c128][n72]
#define SB_L   54272                  // 18432
#define EKR    72704                  // 35840: ek fp32 [128][70] / p staging
#define KA_SMEM 108544
// kc
#define KC_BH  34816                  // 17408: p hi [n64][k136]
#define KC_BL  52224                  // 17408
#define KC_SMEM 69632

// ------------------------------ scratch (__device__ globals, no allocs)
__device__ __align__(16) __nv_bfloat16 g_w_hi[384*128];
__device__ __align__(16) __nv_bfloat16 g_w_lo[384*128];
__device__ __align__(16) __nv_bfloat16 g_pt_hi[(size_t)Bz*NN*HID];
__device__ __align__(16) __nv_bfloat16 g_pt_lo[(size_t)Bz*NN*HID];
__device__ float g_cpart[(size_t)Bz*NHh*NSPLIT*32*32];
__device__ float g_kpart[(size_t)Bz*NHh*NSPLIT*32];
__device__ __align__(16) __nv_bfloat16 g_m_hi[(size_t)Bz*HID*HID];
__device__ __align__(16) __nv_bfloat16 g_m_lo[(size_t)Bz*HID*HID];
__device__ float g_part[Bz*64*2];

typedef unsigned long long u64;
__device__ __forceinline__ u64 pack2(float a, float b){
    u64 r; asm("mov.b64 %0, {%1, %2};" : "=l"(r) : "f"(a), "f"(b)); return r;
}
__device__ __forceinline__ u64 fma2(u64 a, u64 b, u64 c){
    u64 d; asm("fma.rn.f32x2 %0, %1, %2, %3;" : "=l"(d) : "l"(a), "l"(b), "l"(c)); return d;
}
__device__ __forceinline__ float2 unpack2(u64 a){
    float2 f; asm("mov.b64 {%0, %1}, %2;" : "=f"(f.x), "=f"(f.y) : "l"(a)); return f;
}
__device__ __forceinline__ uint32_t smem_u32(const void* p){
    uint32_t a;
    asm("{ .reg .u64 t; cvta.to.shared.u64 t, %1; cvt.u32.u64 %0, t; }"
        : "=r"(a) : "l"(p));
    return a;
}
__device__ __forceinline__ void ldsm4(uint32_t* r, uint32_t addr){
    asm volatile("ldmatrix.sync.aligned.m8n8.x4.shared.b16 {%0,%1,%2,%3}, [%4];"
        : "=r"(r[0]), "=r"(r[1]), "=r"(r[2]), "=r"(r[3]) : "r"(addr));
}
__device__ __forceinline__ void ldsm4t(uint32_t* r, uint32_t addr){
    asm volatile("ldmatrix.sync.aligned.m8n8.x4.trans.shared.b16 {%0,%1,%2,%3}, [%4];"
        : "=r"(r[0]), "=r"(r[1]), "=r"(r[2]), "=r"(r[3]) : "r"(addr));
}
__device__ __forceinline__ void mma_bf16(float* d, const uint32_t* a, const uint32_t* b){
    asm volatile("mma.sync.aligned.m16n8k16.row.col.f32.bf16.bf16.f32 "
        "{%0,%1,%2,%3}, {%4,%5,%6,%7}, {%8,%9}, {%0,%1,%2,%3};"
        : "+f"(d[0]), "+f"(d[1]), "+f"(d[2]), "+f"(d[3])
        : "r"(a[0]), "r"(a[1]), "r"(a[2]), "r"(a[3]), "r"(b[0]), "r"(b[1]));
}

// ------------------------------ shared GEMM machinery
__device__ __forceinline__ void stage_A(char* smem, const uint4* __restrict__ src, int tid){
    __nv_bfloat16* A = (__nv_bfloat16*)(smem + SA);
#pragma unroll
    for (int q=0;q<8;q++){
        int idx = tid + q*256;              // 2048 uint4 = [128][16]
        int r = idx >> 4, c8 = (idx & 15)*8;
        *(uint4*)(A + r*PADB + c8) = src[idx];
    }
}

// B in [k rows][n cols] (ka: x tile), trans ldsm
__device__ __forceinline__ void ld_frag_t(uint32_t aAddr, uint32_t bAddr,
                                          uint32_t aF[2][4], uint32_t bF[4][2]){
    ldsm4(aF[0], aAddr);
    ldsm4(aF[1], aAddr + 16*PADB*2);
    uint32_t r4[4];
    ldsm4t(r4, bAddr);
    bF[0][0]=r4[0]; bF[0][1]=r4[1]; bF[1][0]=r4[2]; bF[1][1]=r4[3];
    ldsm4t(r4, bAddr + 32);
    bF[2][0]=r4[0]; bF[2][1]=r4[1]; bF[3][0]=r4[2]; bF[3][1]=r4[3];
}
__device__ __forceinline__ void hmma_pass_t(uint32_t aAddr, uint32_t bAddr,
                                            float acc[2][4][4]){
    uint32_t aF[2][2][4], bF[2][4][2];
    ld_frag_t(aAddr, bAddr, aF[0], bF[0]);
#pragma unroll
    for (int ks=0; ks<8; ks++){
        int cur = ks & 1;
        if (ks < 7)
            ld_frag_t(aAddr + (ks+1)*32, bAddr + (ks+1)*(16*BSTR*2),
                      aF[cur^1], bF[cur^1]);
#pragma unroll
        for (int mt=0;mt<2;mt++)
#pragma unroll
            for (int ntl=0;ntl<4;ntl++)
                mma_bf16(acc[mt][ntl], aF[cur][mt], bF[cur][ntl]);
    }
}

// B in [n rows][k cols] (kc: p tile), non-trans ldsm
__device__ __forceinline__ void ld_frag_nt(uint32_t aAddr, uint32_t bAddr,
                                           uint32_t aF[2][4], uint32_t bF[4][2]){
    ldsm4(aF[0], aAddr);
    ldsm4(aF[1], aAddr + 16*PADB*2);
    uint32_t r4[4];
    ldsm4(r4, bAddr);
    bF[0][0]=r4[0]; bF[0][1]=r4[1]; bF[1][0]=r4[2]; bF[1][1]=r4[3];
    ldsm4(r4, bAddr + 16*PADB*2);
    bF[2][0]=r4[0]; bF[2][1]=r4[1]; bF[3][0]=r4[2]; bF[3][1]=r4[3];
}
__device__ __forceinline__ void hmma_pass_nt(uint32_t aAddr, uint32_t bAddr,
                                             float acc[2][4][4]){
    uint32_t aF[2][2][4], bF[2][4][2];
    ld_frag_nt(aAddr, bAddr, aF[0], bF[0]);
#pragma unroll
    for (int ks=0; ks<8; ks++){
        int cur = ks & 1;
        if (ks < 7)
            ld_frag_nt(aAddr + (ks+1)*32, bAddr + (ks+1)*32, aF[cur^1], bF[cur^1]);
#pragma unroll
        for (int mt=0;mt<2;mt++)
#pragma unroll
            for (int ntl=0;ntl<4;ntl++)
                mma_bf16(acc[mt][ntl], aF[cur][mt], bF[cur][ntl]);
    }
}

__device__ __forceinline__ void zero_acc(float acc[2][4][4]){
#pragma unroll
    for (int i=0;i<2;i++)
#pragma unroll
        for (int j=0;j<4;j++)
#pragma unroll
            for (int r=0;r<4;r++) acc[i][j][r] = 0.f;
}

// 3-pass GEMM, A restaged (hi, then lo), acc accumulates across passes
__device__ __forceinline__ void gemm3_t(char* smem, const uint4* wh, const uint4* wl,
        int tid, uint32_t aAddr, uint32_t bAH, uint32_t bAL, float acc[2][4][4]){
    __syncthreads();
    stage_A(smem, wh, tid);
    __syncthreads();
    hmma_pass_t(aAddr, bAH, acc);
    hmma_pass_t(aAddr, bAL, acc);
    __syncthreads();
    stage_A(smem, wl, tid);
    __syncthreads();
    hmma_pass_t(aAddr, bAH, acc);
}

// ------------------------------ prep: split W
__global__ void __launch_bounds__(256) prep_w(const float* __restrict__ w){
    int i = blockIdx.x*256 + threadIdx.x;
    if (i < 384*128){
        float v = w[i];
        __nv_bfloat16 h = __float2bfloat16(v);
        g_w_hi[i] = h;
        g_w_lo[i] = __float2bfloat16(v - __bfloat162float(h));
    }
}

// ------------------------------ KA
__global__ void __launch_bounds__(256, 2) ka(const float* __restrict__ x){
    extern __shared__ char smem[];
    const int tid = threadIdx.x, wid = tid >> 5, lane = tid & 31;
    const int nt = blockIdx.x, b = blockIdx.y;
    const int wm = wid & 3, wn = wid >> 2;        // 4 M-warps x 2 N-warps (32 cols)
    const uint32_t sbase = smem_u32(smem);
    const int g = lane >> 2, tq = lane & 3;

    // ---- stage SB = x bf16 hi/lo [c=128][n=64]
    {
        __nv_bfloat16* Bh = (__nv_bfloat16*)(smem + SB_H);
        __nv_bfloat16* Bl = (__nv_bfloat16*)(smem + SB_L);
        const float* xb = x + (size_t)b*HID*NN + (size_t)nt*64;
#pragma unroll
        for (int q=0;q<8;q++){
            int idx = tid + q*256;                // 2048 float4
            int c = idx >> 4, n4 = (idx & 15)*4;
            float4 v = *(const float4*)(xb + (size_t)c*NN + n4);
            __nv_bfloat16 h0 = __float2bfloat16(v.x), h1 = __float2bfloat16(v.y);
            __nv_bfloat16 h2 = __float2bfloat16(v.z), h3 = __float2bfloat16(v.w);
            __nv_bfloat162 H0; H0.x=h0; H0.y=h1;
            __nv_bfloat162 H1; H1.x=h2; H1.y=h3;
            __nv_bfloat162 L0, L1;
            L0.x = __float2bfloat16(v.x - __bfloat162float(h0));
            L0.y = __float2bfloat16(v.y - __bfloat162float(h1));
            L1.x = __float2bfloat16(v.z - __bfloat162float(h2));
            L1.y = __float2bfloat16(v.w - __bfloat162float(h3));
            *(__nv_bfloat162*)(Bh + c*BSTR + n4)     = H0;
            *(__nv_bfloat162*)(Bh + c*BSTR + n4 + 2) = H1;
            *(__nv_bfloat162*)(Bl + c*BSTR + n4)     = L0;
            *(__nv_bfloat162*)(Bl + c*BSTR + n4 + 2) = L1;
        }
    }

    const uint32_t aAddr = sbase + SA +
        (uint32_t)(((wm*32 + (lane & 15))*PADB + ((lane >> 4) << 3))*2);
    const uint32_t bAH = sbase + SB_H +
        (uint32_t)((((((lane >> 3) & 1) << 3) + (lane & 7))*BSTR + wn*32 + ((lane >> 4) << 3))*2);
    const uint32_t bAL = bAH + (SB_L - SB_H);

    float acc[2][4][4];

    // ============ K projection ============
    zero_acc(acc);
    gemm3_t(smem, (const uint4*)g_w_hi + 2048, (const uint4*)g_w_lo + 2048,
            tid, aAddr, bAH, bAL, acc);
    {   // ek -> EKR (fp32), thread-private region
        float* ekS = (float*)(smem + EKR);
#pragma unroll
        for (int mt=0;mt<2;mt++)
#pragma unroll
            for (int ntl=0;ntl<4;ntl++)
#pragma unroll
                for (int r=0;r<4;r++){
                    int o = wm*32 + mt*16 + g + ((r>>1)<<3);
                    int n = wn*32 + ntl*8 + tq*2 + (r&1);
                    ekS[o*EKST + n] = __expf(acc[mt][ntl][r]);
                }
    }

    // ============ V projection ============
    zero_acc(acc);
    gemm3_t(smem, (const uint4*)g_w_hi + 4096, (const uint4*)g_w_lo + 4096,
            tid, aAddr, bAH, bAL, acc);
    __syncthreads();                 // all pass-3 SA reads done
    {   // v -> SA (fp32)
        float* vS = (float*)(smem + SA);
#pragma unroll
        for (int mt=0;mt<2;mt++)
#pragma unroll
            for (int ntl=0;ntl<4;ntl++)
#pragma unroll
                for (int r=0;r<4;r++){
                    int o = wm*32 + mt*16 + g + ((r>>1)<<3);
                    int n = wn*32 + ntl*8 + tq*2 + (r&1);
                    vS[o*EKST + n] = acc[mt][ntl][r];
                }
    }
    __syncthreads();

    // ============ ctx partials ============
    {
        const float* ekS = (const float*)(smem + EKR);
        const float* vS  = (const float*)(smem + SA);
        const int h = wid >> 1, eh = wid & 1;
        const int dq = lane & 7, eq = lane >> 3;
        const float* ekp = ekS + (h*32 + dq*4)*EKST;
        const float* vp  = vS  + (h*32 + eh*16 + eq*4)*EKST;
        u64 c2[4][4];
        float kdv[4] = {0.f,0.f,0.f,0.f};
#pragma unroll
        for (int i=0;i<4;i++)
#pragma unroll
            for (int j=0;j<4;j++) c2[i][j] = 0ull;
        for (int n2=0;n2<32;n2++){
            float2 e2[4], v2[4];
#pragma unroll
            for (int i=0;i<4;i++) e2[i] = *(const float2*)(ekp + i*EKST + 2*n2);
#pragma unroll
            for (int j=0;j<4;j++) v2[j] = *(const float2*)(vp  + j*EKST + 2*n2);
            u64 ep[4], vv[4];
#pragma unroll
            for (int i=0;i<4;i++) ep[i] = pack2(e2[i].x, e2[i].y);
#pragma unroll
            for (int j=0;j<4;j++) vv[j] = pack2(v2[j].x, v2[j].y);
#pragma unroll
            for (int i=0;i<4;i++)
#pragma unroll
                for (int j=0;j<4;j++) c2[i][j] = fma2(ep[i], vv[j], c2[i][j]);
            if (eq == 0 && eh == 0){
#pragma unroll
                for (int i=0;i<4;i++) kdv[i] += e2[i].x + e2[i].y;
            }
        }
        const size_t pb = ((size_t)(b*NHh + h))*NSPLIT + nt;
        float* cp = g_cpart + pb*1024;
#pragma unroll
        for (int i=0;i<4;i++)
#pragma unroll
            for (int j=0;j<4;j++){
                float2 t = unpack2(c2[i][j]);
                cp[(dq*4+i)*32 + eh*16 + eq*4 + j] = t.x + t.y;
            }
        if (eq == 0 && eh == 0){
#pragma unroll
            for (int i=0;i<4;i++) g_kpart[pb*32 + dq*4 + i] = kdv[i];
        }
    }

    // ============ Q projection + softmax ============
    zero_acc(acc);
    gemm3_t(smem, (const uint4*)g_w_hi, (const uint4*)g_w_lo,
            tid, aAddr, bAH, bAL, acc);   // leading sync orders ctx SA reads
    {
#pragma unroll
        for (int mt=0;mt<2;mt++)
#pragma unroll
            for (int ntl=0;ntl<4;ntl++)
#pragma unroll
                for (int r=0;r<4;r++) acc[mt][ntl][r] = __expf(acc[mt][ntl][r]);
        // warp wm == head wm: column sums over 32 rows within warp
#pragma unroll
        for (int ntl=0;ntl<4;ntl++){
            float se = acc[0][ntl][0]+acc[0][ntl][2]+acc[1][ntl][0]+acc[1][ntl][2];
            float so = acc[0][ntl][1]+acc[0][ntl][3]+acc[1][ntl][1]+acc[1][ntl][3];
#pragma unroll
            for (int m=4;m<32;m<<=1){
                se += __shfl_xor_sync(0xffffffffu, se, m);
                so += __shfl_xor_sync(0xffffffffu, so, m);
            }
            float fe = SCALE/se, fo = SCALE/so;
            acc[0][ntl][0]*=fe; acc[0][ntl][2]*=fe;
            acc[1][ntl][0]*=fe; acc[1][ntl][2]*=fe;
            acc[0][ntl][1]*=fo; acc[0][ntl][3]*=fo;
            acc[1][ntl][1]*=fo; acc[1][ntl][3]*=fo;
        }
        // p hi/lo -> EKR staging [o][n] (stride 66), then coalesced write
        unsigned short* ph = (unsigned short*)(smem + EKR);
        unsigned short* pl = ph + 128*66;
#pragma unroll
        for (int mt=0;mt<2;mt++)
#pragma unroll
            for (int ntl=0;ntl<4;ntl++)
#pragma unroll
                for (int r=0;r<4;r++){
                    int o = wm*32 + mt*16 + g + ((r>>1)<<3);
                    int n = wn*32 + ntl*8 + tq*2 + (r&1);
                    float v = acc[mt][ntl][r];
                    __nv_bfloat16 hv = __float2bfloat16(v);
                    __nv_bfloat16 lv = __float2bfloat16(v - __bfloat162float(hv));
                    ph[o*66 + n] = __bfloat16_as_ushort(hv);
                    pl[o*66 + n] = __bfloat16_as_ushort(lv);
                }
        __syncthreads();
        {
            const size_t gb = (size_t)b*NN + (size_t)nt*64;
            uint32_t* gh = (uint32_t*)g_pt_hi;
            uint32_t* gl = (uint32_t*)g_pt_lo;
#pragma unroll
            for (int q=0;q<16;q++){
                int idx = tid + q*256;            // 4096
                int n = idx >> 6, u = idx & 63;
                uint32_t hv = (uint32_t)ph[(2*u)*66 + n] | ((uint32_t)ph[(2*u+1)*66 + n] << 16);
                uint32_t lv = (uint32_t)pl[(2*u)*66 + n] | ((uint32_t)pl[(2*u+1)*66 + n] << 16);
                gh[(gb + n)*64 + u] = hv;
                gl[(gb + n)*64 + u] = lv;
            }
        }
    }
}

// ------------------------------ KB2: reduce ctx, fold w_out -> M2 bf16 hi/lo
__global__ void __launch_bounds__(256) kb2(const float* __restrict__ wout){
    const int h = blockIdx.x, b = blockIdx.y;
    __shared__ float sctx[32][33];
    __shared__ float kds[32];
    __shared__ float sW[128][33];
    const int tid = threadIdx.x;
    const size_t pbase = ((size_t)(b*NHh+h))*NSPLIT;

    if (tid < 32){
        float s = 0.f;
        for (int si=0; si<NSPLIT; si++) s += g_kpart[(pbase+si)*32 + tid];
        kds[tid] = s;
    }
#pragma unroll
    for (int q=0;q<16;q++){
        int idx = tid + q*256;
        int o = idx >> 5, e = idx & 31;
        sW[o][e] = wout[o*HID + h*32 + e];
    }
    __syncthreads();
    {
        float4 s = make_float4(0.f,0.f,0.f,0.f);
        for (int si=0; si<NSPLIT; si++){
            float4 p = *(const float4*)(g_cpart + (pbase+si)*1024 + tid*4);
            s.x+=p.x; s.y+=p.y; s.z+=p.z; s.w+=p.w;
        }
        int d = tid >> 3, e0 = (tid & 7)*4;
        float inv = 1.0f / kds[d];
        sctx[d][e0+0]=s.x*inv; sctx[d][e0+1]=s.y*inv;
        sctx[d][e0+2]=s.z*inv; sctx[d][e0+3]=s.w*inv;
    }
    __syncthreads();
    {
        int o = tid & 127, dh = (tid >> 7)*16;
        float m[16];
#pragma unroll
        for (int dd=0;dd<16;dd++) m[dd]=0.f;
        for (int e=0;e<32;e++){
            float wv = sW[o][e];
#pragma unroll
            for (int dd=0;dd<16;dd++) m[dd] += wv * sctx[dh+dd][e];
        }
#pragma unroll
        for (int dd=0;dd<16;dd++){
            __nv_bfloat16 hv = __float2bfloat16(m[dd]);
            size_t a = ((size_t)b*HID + o)*HID + h*32 + dh + dd;
            g_m_hi[a] = hv;
            g_m_lo[a] = __float2bfloat16(m[dd] - __bfloat162float(hv));
        }
    }
}

// ------------------------------ KC: HMMA out-proj, n-tile 64
__global__ void __launch_bounds__(256, 2) kc(const float* __restrict__ bout,
                                             float* __restrict__ out){
    extern __shared__ char smem[];
    __shared__ float red1[8], red2[8];
    const int tid = threadIdx.x, wid = tid >> 5, lane = tid & 31;
    const int nt = blockIdx.x, b = blockIdx.y;
    const int wm = wid & 3, wn = wid >> 2;
    const uint32_t sbase = smem_u32(smem);
    const int g = lane >> 2, tq = lane & 3;

    // stage B = p tile hi/lo [n=64][k=128]
    {
        const uint4* ph = (const uint4*)g_pt_hi + ((size_t)b*NN + (size_t)nt*64)*16;
        const uint4* pl = (const uint4*)g_pt_lo + ((size_t)b*NN + (size_t)nt*64)*16;
        __nv_bfloat16* Bh = (__nv_bfloat16*)(smem + KC_BH);
        __nv_bfloat16* Bl = (__nv_bfloat16*)(smem + KC_BL);
#pragma unroll
        for (int q=0;q<4;q++){
            int idx = tid + q*256;                 // 1024 uint4
            int r = idx >> 4, c8 = (idx & 15)*8;
            *(uint4*)(Bh + r*PADB + c8) = ph[idx];
            *(uint4*)(Bl + r*PADB + c8) = pl[idx];
        }
    }

    const uint32_t aAddr = sbase + SA +
        (uint32_t)(((wm*32 + (lane & 15))*PADB + ((lane >> 4) << 3))*2);
    const uint32_t bAddrH = sbase + KC_BH +
        (uint32_t)(((wn*32 + ((lane >> 4) << 3) + (lane & 7))*PADB + (((lane >> 3) & 1) << 3))*2);
    const uint32_t bAddrL = bAddrH + (KC_BL - KC_BH);

    float acc[2][4][4];
    zero_acc(acc);

    stage_A(smem, (const uint4*)g_m_hi + (size_t)b*2048, tid);
    __syncthreads();
    hmma_pass_nt(aAddr, bAddrH, acc);
    hmma_pass_nt(aAddr, bAddrL, acc);
    __syncthreads();
    stage_A(smem, (const uint4*)g_m_lo + (size_t)b*2048, tid);
    __syncthreads();
    hmma_pass_nt(aAddr, bAddrH, acc);

    // epilogue: bias, writes, GN partials
    float bias[4];
#pragma unroll
    for (int r2=0;r2<4;r2++) bias[r2] = bout[wm*32 + r2*8 + g];
    float s1 = 0.f, s2 = 0.f;
#pragma unroll
    for (int mt=0;mt<2;mt++)
#pragma unroll
        for (int ntl=0;ntl<4;ntl++){
#pragma unroll
            for (int half=0; half<2; half++){
                float bv = bias[mt*2 + half];
                float v0 = acc[mt][ntl][half*2+0] + bv;
                float v1 = acc[mt][ntl][half*2+1] + bv;
                s1 += v0 + v1;
                s2 += v0*v0 + v1*v1;
                int row = wm*32 + mt*16 + half*8 + g;
                int col = nt*64 + wn*32 + ntl*8 + tq*2;
                *(float2*)(out + ((size_t)(b*HID + row))*NN + col) = make_float2(v0, v1);
            }
        }
#pragma unroll
    for (int m=1;m<32;m<<=1){
        s1 += __shfl_xor_sync(0xffffffffu, s1, m);
        s2 += __shfl_xor_sync(0xffffffffu, s2, m);
    }
    if (lane == 0){ red1[wid] = s1; red2[wid] = s2; }
    __syncthreads();
    if (tid == 0){
        float a=0.f, c2s=0.f;
#pragma unroll
        for (int w=0; w<8; w++){ a += red1[w]; c2s += red2[w]; }
        g_part[(b*64+nt)*2 + 0] = a;
        g_part[(b*64+nt)*2 + 1] = c2s;
    }
}

// ------------------------------ KD: GroupNorm finalize
__global__ void __launch_bounds__(256) kd(float* __restrict__ out,
                                          const float* __restrict__ gamma,
                                          const float* __restrict__ beta){
    const int cx = blockIdx.x, b = blockIdx.y;
    __shared__ float sm[2];
    const int tid = threadIdx.x;
    if (tid == 0){
        float s=0.f, s2=0.f;
#pragma unroll
        for (int i=0;i<64;i++){
            s  += g_part[(b*64+i)*2 + 0];
            s2 += g_part[(b*64+i)*2 + 1];
        }
        sm[0]=s; sm[1]=s2;
    }
    __syncthreads();
    const float invN = 1.0f / ((float)HID * (float)NN);
    float mean = sm[0]*invN;
    float var  = sm[1]*invN - mean*mean;
    float rstd = rsqrtf(var + 1e-5f);

    float* base = out + (size_t)b*HID*NN + (size_t)cx*16384;
#pragma unroll
    for (int q=0;q<16;q++){
        int fi = tid + q*256;
        int c  = (cx*16384 + fi*4) >> 12;
        float a  = gamma[c]*rstd;
        float bb = beta[c] - mean*a;
        float4 v = *(float4*)(base + fi*4);
        v.x = v.x*a + bb; v.y = v.y*a + bb;
        v.z = v.z*a + bb; v.w = v.w*a + bb;
        *(float4*)(base + fi*4) = v;
    }
}

// ---------------------------------------------------------------------------
extern "C" void kernel_launch(void* const* d_in, const int* in_sizes, int n_in,
                              void* d_out, int out_size){
    (void)in_sizes; (void)n_in; (void)out_size;
    const float* x     = (const float*)d_in[0];
    const float* wqkv  = (const float*)d_in[1];
    const float* wout  = (const float*)d_in[2];
    const float* bout  = (const float*)d_in[3];
    const float* gamma = (const float*)d_in[4];
    const float* beta  = (const float*)d_in[5];
    float* out = (float*)d_out;

    cudaFuncSetAttribute(ka, cudaFuncAttributeMaxDynamicSharedMemorySize, KA_SMEM);
    cudaFuncSetAttribute(kc, cudaFuncAttributeMaxDynamicSharedMemorySize, KC_SMEM);

    prep_w<<<192, 256>>>(wqkv);
    ka <<<dim3(64,32), 256, KA_SMEM>>>(x);
    kb2<<<dim3(4,32),  256>>>(wout);
    kc <<<dim3(64,32), 256, KC_SMEM>>>(bout, out);
    kd <<<dim3(32,32), 256>>>(out, gamma, beta);
}